// round 2
// baseline (speedup 1.0000x reference)
#include <cuda_runtime.h>
#include <cuda_bf16.h>
#include <math.h>

// StatefulSynapseNet: per sample (N=65536):
//   x[n] is [28 f][28 t] (f = row, t = col of the 28x28 image)
//   H[t][o]  = b1[o] + sum_f x[f][t] * W1[o][f]              (o = 0..31)
//   IF scan over t: v += H; s = (v>=1); v = s?0:v
//   synapse:        g = g - g*sigmoid(w_syn) + s ; y[t][o] = g
//   H2[t][j] = b2[j] + sum_o y[t][o] * W2[j][o]              (j = 0..9)
//   IF scan over t on H2 -> spikes s2; out[n][j] = mean_t s2
//
// Decomposition: 1 warp = 1 sample. Lane = o for phase 1 (GEMM1 + scans in
// registers), y goes through padded shared, lane = t for phase 2 (GEMM2),
// lane = j for the final scan. All math fp32; GEMMs use packed fma.rn.f32x2.

typedef unsigned long long ull;

__device__ __forceinline__ ull pack2(float lo, float hi) {
    ull r;
    asm("mov.b64 %0, {%1,%2};" : "=l"(r) : "f"(lo), "f"(hi));
    return r;
}
__device__ __forceinline__ void unpack2(ull v, float& lo, float& hi) {
    asm("mov.b64 {%0,%1}, %2;" : "=f"(lo), "=f"(hi) : "l"(v));
}
__device__ __forceinline__ ull ffma2(ull a, ull b, ull c) {
    ull d;
    asm("fma.rn.f32x2 %0, %1, %2, %3;" : "=l"(d) : "l"(a), "l"(b), "l"(c));
    return d;
}

#define WARPS 4              // samples per block
#define T_DIM 28
#define F_DIM 28
#define C1 32
#define C2 10
#define Y_PITCH 34           // pad: lanes differ by 34 -> <=2-way conflict, 8B aligned rows

__global__ __launch_bounds__(WARPS * 32)
void snn_kernel(const float* __restrict__ x,
                const float* __restrict__ W1,
                const float* __restrict__ b1,
                const float* __restrict__ w_syn,
                const float* __restrict__ W2,
                const float* __restrict__ b2,
                float* __restrict__ out,
                int N)
{
    __shared__ __align__(16) float sh_x[WARPS * F_DIM * T_DIM];   // [warp][f][t]
    __shared__ __align__(16) float sh_y[WARPS * T_DIM * Y_PITCH]; // [warp][t][o] padded
    __shared__ __align__(16) float sh_h2[WARPS * C2 * T_DIM];     // [warp][j][t]
    __shared__ __align__(16) float sh_W2[C2 * C1];
    __shared__ float sh_b2[C2];

    const int tid  = threadIdx.x;
    const int lane = tid & 31;
    const int warp = tid >> 5;
    const int n0   = blockIdx.x * WARPS;
    const int n    = n0 + warp;

    // ---- cooperative loads: x tile (coalesced float4) + W2/b2 ----
    {
        int nspl = N - n0; if (nspl > WARPS) nspl = WARPS;
        const float4* gx = reinterpret_cast<const float4*>(x + (size_t)n0 * (F_DIM * T_DIM));
        float4* sx4 = reinterpret_cast<float4*>(sh_x);
        const int tot4 = nspl * (F_DIM * T_DIM / 4);
        for (int i = tid; i < tot4; i += WARPS * 32) sx4[i] = gx[i];
        for (int i = tid; i < C2 * C1; i += WARPS * 32) sh_W2[i] = W2[i];
        if (tid < C2) sh_b2[tid] = b2[tid];
    }
    __syncthreads();

    if (n >= N) return;

    const float wsv = __ldg(w_syn);
    const float inv_tau = 1.0f / (1.0f + expf(-wsv));

    // ---- per-lane weights: W1 row for channel o = lane ----
    float w1r[F_DIM];
#pragma unroll
    for (int f = 0; f < F_DIM; ++f) w1r[f] = __ldg(&W1[lane * F_DIM + f]);
    const float b1o = __ldg(&b1[lane]);

    float* sxw = sh_x + warp * (F_DIM * T_DIM);

    // ---- phase 1: H[t][o] for all 28 t in 14 packed f32x2 accumulators ----
    ull acc[T_DIM / 2];
    {
        const ull binit = pack2(b1o, b1o);
#pragma unroll
        for (int p = 0; p < T_DIM / 2; ++p) acc[p] = binit;
    }
#pragma unroll 4
    for (int f = 0; f < F_DIM; ++f) {
        const ull wp = pack2(w1r[f], w1r[f]);
        const ulonglong2* xr = reinterpret_cast<const ulonglong2*>(sxw + f * T_DIM);
#pragma unroll
        for (int q = 0; q < 7; ++q) {                 // 7 x LDS.128 = 28 t values
            ulonglong2 xv = xr[q];
            acc[2 * q]     = ffma2(xv.x, wp, acc[2 * q]);
            acc[2 * q + 1] = ffma2(xv.y, wp, acc[2 * q + 1]);
        }
    }

    // ---- IF scan + synapse filter (lane = o), write y to shared ----
    float* syw = sh_y + warp * (T_DIM * Y_PITCH);
    {
        float v = 0.0f, g = 0.0f;
#pragma unroll
        for (int t = 0; t < T_DIM; ++t) {
            float hlo, hhi;
            unpack2(acc[t >> 1], hlo, hhi);
            float h = (t & 1) ? hhi : hlo;
            v += h;
            bool sp = (v >= 1.0f);
            float s = sp ? 1.0f : 0.0f;
            v = sp ? 0.0f : v;                         // hard reset
            g = fmaf(g, -inv_tau, g) + s;              // g - g*inv_tau + s
            syw[t * Y_PITCH + lane] = g;
        }
    }
    __syncwarp();

    // ---- phase 2: H2[t][j] (lane = t, 28 active lanes) ----
    float* sh2w = sh_h2 + warp * (C2 * T_DIM);
    if (lane < T_DIM) {
        ull yv[C1 / 2];
        const ull* yr = reinterpret_cast<const ull*>(syw + lane * Y_PITCH);
#pragma unroll
        for (int q = 0; q < C1 / 2; ++q) yv[q] = yr[q];
#pragma unroll
        for (int j = 0; j < C2; ++j) {
            ull a2 = pack2(0.0f, 0.0f);
            const ulonglong2* wr = reinterpret_cast<const ulonglong2*>(sh_W2 + j * C1);
#pragma unroll
            for (int q2 = 0; q2 < C1 / 4; ++q2) {
                ulonglong2 wv = wr[q2];
                a2 = ffma2(yv[2 * q2],     wv.x, a2);
                a2 = ffma2(yv[2 * q2 + 1], wv.y, a2);
            }
            float alo, ahi;
            unpack2(a2, alo, ahi);
            sh2w[j * T_DIM + lane] = alo + ahi + sh_b2[j];
        }
    }
    __syncwarp();

    // ---- second IF scan + mean (lane = j, 10 active lanes) ----
    if (lane < C2) {
        float v = 0.0f, cnt = 0.0f;
#pragma unroll
        for (int t = 0; t < T_DIM; ++t) {
            v += sh2w[lane * T_DIM + t];
            if (v >= 1.0f) { cnt += 1.0f; v = 0.0f; }
        }
        out[(size_t)n * C2 + lane] = cnt * (1.0f / 28.0f);
    }
}

extern "C" void kernel_launch(void* const* d_in, const int* in_sizes, int n_in,
                              void* d_out, int out_size)
{
    const float* x     = (const float*)d_in[0];
    const float* W1    = (const float*)d_in[1];
    const float* b1    = (const float*)d_in[2];
    const float* w_syn = (const float*)d_in[3];
    const float* W2    = (const float*)d_in[4];
    const float* b2    = (const float*)d_in[5];
    float* out = (float*)d_out;

    const int N = in_sizes[0] / (F_DIM * T_DIM);
    const int blocks = (N + WARPS - 1) / WARPS;
    snn_kernel<<<blocks, WARPS * 32>>>(x, W1, b1, w_syn, W2, b2, out, N);
}

// round 3
// speedup vs baseline: 1.1728x; 1.1728x over previous
#include <cuda_runtime.h>
#include <cuda_bf16.h>
#include <math.h>

// StatefulSynapseNet: per sample (N=65536):
//   x[n] is [28 f][28 t]
//   H[t][o]  = b1[o] + sum_f x[f][t] * W1[o][f]              (o = 0..31)
//   IF scan over t: v += H; s = (v>=1); v = s?0:v
//   synapse:        g = g - g*sigmoid(w_syn) + s ; y[t][o] = g
//   H2[t][j] = b2[j] + sum_o y[t][o] * W2[j][o]              (j = 0..9)
//   IF scan over t on H2 -> spikes s2; out[n][j] = mean_t s2
//
// Decomposition: 1 warp = 1 sample. Lane = o for phase 1, lane = t for the
// second GEMM, lane = j for the final scan. All fp32, GEMMs via fma.rn.f32x2.
// R3 change: W1 staged in shared (pitch 29, conflict-free) instead of the
// strided-LDG register preload that generated ~784 L1 wavefronts/sample.
// y overlays the dead x region; h2 padded to pitch 29 (conflict-free).

typedef unsigned long long ull;

__device__ __forceinline__ ull pack2(float lo, float hi) {
    ull r;
    asm("mov.b64 %0, {%1,%2};" : "=l"(r) : "f"(lo), "f"(hi));
    return r;
}
__device__ __forceinline__ void unpack2(ull v, float& lo, float& hi) {
    asm("mov.b64 {%0,%1}, %2;" : "=f"(lo), "=f"(hi) : "l"(v));
}
__device__ __forceinline__ ull ffma2(ull a, ull b, ull c) {
    ull d;
    asm("fma.rn.f32x2 %0, %1, %2, %3;" : "=l"(d) : "l"(a), "l"(b), "l"(c));
    return d;
}

#define WARPS 4              // samples per block
#define T_DIM 28
#define F_DIM 28
#define C1 32
#define C2 10
#define Y_PITCH 34           // 8B-aligned rows; phase-2 LDS.64 is only 2-way
#define H2_PITCH 29          // conflict-free for both store (lane=t) and read (lane=j)
#define W1_PITCH 29          // gcd(29,32)=1 -> per-lane row reads conflict-free
#define REGION 1244          // per-warp floats: max(x 784, y 952) + h2 290, 16B-mult

__global__ __launch_bounds__(WARPS * 32)
void snn_kernel(const float* __restrict__ x,
                const float* __restrict__ W1,
                const float* __restrict__ b1,
                const float* __restrict__ w_syn,
                const float* __restrict__ W2,
                const float* __restrict__ b2,
                float* __restrict__ out,
                int N)
{
    __shared__ __align__(16) float sh_buf[WARPS * REGION];  // per-warp x/y + h2
    __shared__ __align__(16) float sh_W1[C1 * W1_PITCH];
    __shared__ __align__(16) float sh_W2[C2 * C1];
    __shared__ float sh_b2[C2];

    const int tid  = threadIdx.x;
    const int lane = tid & 31;
    const int warp = tid >> 5;
    const int n0   = blockIdx.x * WARPS;
    const int n    = n0 + warp;

    // ---- cooperative loads: x tile (coalesced float4) + W1 (padded) + W2/b2 ----
    {
        int nspl = N - n0; if (nspl > WARPS) nspl = WARPS;
        const float4* gx = reinterpret_cast<const float4*>(x + (size_t)n0 * (F_DIM * T_DIM));
        const int tot4 = nspl * (F_DIM * T_DIM / 4);
        for (int i = tid; i < tot4; i += WARPS * 32) {
            float4 v = gx[i];
            int s4 = i / (F_DIM * T_DIM / 4);            // which sample
            int r4 = i - s4 * (F_DIM * T_DIM / 4);
            reinterpret_cast<float4*>(sh_buf + s4 * REGION)[r4] = v;
        }
        for (int i = tid; i < C1 * F_DIM; i += WARPS * 32) {
            int o = i / F_DIM, f = i - o * F_DIM;
            sh_W1[o * W1_PITCH + f] = W1[i];
        }
        for (int i = tid; i < C2 * C1; i += WARPS * 32) sh_W2[i] = W2[i];
        if (tid < C2) sh_b2[tid] = b2[tid];
    }
    __syncthreads();

    if (n >= N) return;

    const float wsv = __ldg(w_syn);
    const float inv_tau = 1.0f / (1.0f + expf(-wsv));

    // ---- per-lane W1 row (channel o = lane), conflict-free LDS ----
    float w1r[F_DIM];
#pragma unroll
    for (int f = 0; f < F_DIM; ++f) w1r[f] = sh_W1[lane * W1_PITCH + f];
    const float b1o = __ldg(&b1[lane]);

    float* sxw = sh_buf + warp * REGION;                 // x: [f][t], 784 floats

    // ---- phase 1: H[t][o] for all 28 t in 14 packed f32x2 accumulators ----
    ull acc[T_DIM / 2];
    {
        const ull binit = pack2(b1o, b1o);
#pragma unroll
        for (int p = 0; p < T_DIM / 2; ++p) acc[p] = binit;
    }
#pragma unroll 4
    for (int f = 0; f < F_DIM; ++f) {
        const ull wp = pack2(w1r[f], w1r[f]);
        const ulonglong2* xr = reinterpret_cast<const ulonglong2*>(sxw + f * T_DIM);
#pragma unroll
        for (int q = 0; q < 7; ++q) {                    // 7 x LDS.128 broadcast
            ulonglong2 xv = xr[q];
            acc[2 * q]     = ffma2(xv.x, wp, acc[2 * q]);
            acc[2 * q + 1] = ffma2(xv.y, wp, acc[2 * q + 1]);
        }
    }
    __syncwarp();                                        // x fully read -> safe to overlay y

    // ---- IF scan + synapse filter (lane = o), write y over the x region ----
    float* syw = sxw;                                    // y: [t][o] pitch 34
    {
        float v = 0.0f, g = 0.0f;
#pragma unroll
        for (int t = 0; t < T_DIM; ++t) {
            float hlo, hhi;
            unpack2(acc[t >> 1], hlo, hhi);
            float h = (t & 1) ? hhi : hlo;
            v += h;
            bool sp = (v >= 1.0f);
            float s = sp ? 1.0f : 0.0f;
            v = sp ? 0.0f : v;                           // hard reset
            g = fmaf(g, -inv_tau, g) + s;                // g - g*inv_tau + s
            syw[t * Y_PITCH + lane] = g;
        }
    }
    __syncwarp();

    // ---- phase 2: H2[t][j] (lane = t, 28 active lanes) ----
    float* sh2w = sxw + T_DIM * Y_PITCH;                 // h2: [j][t] pitch 29
    if (lane < T_DIM) {
        ull yv[C1 / 2];
        const ull* yr = reinterpret_cast<const ull*>(syw + lane * Y_PITCH);
#pragma unroll
        for (int q = 0; q < C1 / 2; ++q) yv[q] = yr[q];
#pragma unroll
        for (int j = 0; j < C2; ++j) {
            ull a2 = pack2(0.0f, 0.0f);
            const ulonglong2* wr = reinterpret_cast<const ulonglong2*>(sh_W2 + j * C1);
#pragma unroll
            for (int q2 = 0; q2 < C1 / 4; ++q2) {
                ulonglong2 wv = wr[q2];
                a2 = ffma2(yv[2 * q2],     wv.x, a2);
                a2 = ffma2(yv[2 * q2 + 1], wv.y, a2);
            }
            float alo, ahi;
            unpack2(a2, alo, ahi);
            sh2w[j * H2_PITCH + lane] = alo + ahi + sh_b2[j];
        }
    }
    __syncwarp();

    // ---- second IF scan + mean (lane = j, 10 active lanes) ----
    if (lane < C2) {
        float v = 0.0f, cnt = 0.0f;
#pragma unroll
        for (int t = 0; t < T_DIM; ++t) {
            v += sh2w[lane * H2_PITCH + t];
            if (v >= 1.0f) { cnt += 1.0f; v = 0.0f; }
        }
        out[(size_t)n * C2 + lane] = cnt * (1.0f / 28.0f);
    }
}

extern "C" void kernel_launch(void* const* d_in, const int* in_sizes, int n_in,
                              void* d_out, int out_size)
{
    const float* x     = (const float*)d_in[0];
    const float* W1    = (const float*)d_in[1];
    const float* b1    = (const float*)d_in[2];
    const float* w_syn = (const float*)d_in[3];
    const float* W2    = (const float*)d_in[4];
    const float* b2    = (const float*)d_in[5];
    float* out = (float*)d_out;

    const int N = in_sizes[0] / (F_DIM * T_DIM);
    const int blocks = (N + WARPS - 1) / WARPS;
    snn_kernel<<<blocks, WARPS * 32>>>(x, W1, b1, w_syn, W2, b2, out, N);
}

// round 4
// speedup vs baseline: 1.5259x; 1.3011x over previous
#include <cuda_runtime.h>
#include <math.h>

// StatefulSynapseNet, R4: weights in __constant__ (uniform/const port),
// x via direct coalesced LDG with lane=t, shared used only for the two
// warp-local transposes (odd pitches -> conflict-free scalar LDS/STS).
//
// Per sample n:
//   H[t][o]  = b1[o] + sum_f x[f][t] * W1[o][f]
//   IF scan over t (v+=H; s=v>=1; v=s?0:v)
//   g = g - g*sigmoid(w_syn) + s ; y[t][o]=g
//   H2[t][j] = b2[j] + sum_o y[t][o]*W2[j][o]
//   IF scan -> s2 ; out[n][j] = mean_t s2

typedef unsigned long long ull;

__device__ __forceinline__ ull pack2(float lo, float hi) {
    ull r; asm("mov.b64 %0, {%1,%2};" : "=l"(r) : "f"(lo), "f"(hi)); return r;
}
__device__ __forceinline__ void unpack2(ull v, float& lo, float& hi) {
    asm("mov.b64 {%0,%1}, %2;" : "=f"(lo), "=f"(hi) : "l"(v));
}
__device__ __forceinline__ ull ffma2(ull a, ull b, ull c) {
    ull d; asm("fma.rn.f32x2 %0, %1, %2, %3;" : "=l"(d) : "l"(a), "l"(b), "l"(c)); return d;
}

#define T_DIM 28
#define F_DIM 28
#define C1 32
#define C2 10
#define WARPS 4
#define HP 33              // H/y pitch: 33 mod 32 = 1 -> scalar row access conflict-free
#define H2P 29             // h2 pitch, conflict-free both directions
#define REGION (T_DIM*HP + C2*H2P + 2)   // 924 + 290 + 2 = 1216 floats per warp

// constant-block layout (floats)
#define OFF_W1T 0          // W1 transposed pairs: [f*32 + o] = W1[o*28+f]
#define OFF_W2  896        // [j*32 + o] (native layout)
#define OFF_B1  1216       // 32
#define OFF_B2  1248       // 10
#define OFF_ITAU 1258      // sigmoid(w_syn)
#define CP_SIZE 1280

__constant__ __align__(16) float c_P[CP_SIZE];
__device__   __align__(16) float g_stage[CP_SIZE];

__global__ void setup_kernel(const float* __restrict__ W1,
                             const float* __restrict__ b1,
                             const float* __restrict__ w_syn,
                             const float* __restrict__ W2,
                             const float* __restrict__ b2)
{
    int i = threadIdx.x;
    for (int idx = i; idx < C1 * F_DIM; idx += 1024) {
        int f = idx >> 5, o = idx & 31;
        g_stage[OFF_W1T + idx] = W1[o * F_DIM + f];
    }
    for (int idx = i; idx < C2 * C1; idx += 1024)
        g_stage[OFF_W2 + idx] = W2[idx];
    if (i < C1) g_stage[OFF_B1 + i] = b1[i];
    if (i < C2) g_stage[OFF_B2 + i] = b2[i];
    if (i == 0) g_stage[OFF_ITAU] = 1.0f / (1.0f + expf(-w_syn[0]));
}

__global__ __launch_bounds__(WARPS * 32, 8)
void snn_kernel(const float* __restrict__ x, float* __restrict__ out, int N)
{
    __shared__ float sh[WARPS * REGION];
    const int lane = threadIdx.x & 31;
    const int warp = threadIdx.x >> 5;
    const int n = blockIdx.x * WARPS + warp;
    if (n >= N) return;

    float* shw = sh + warp * REGION;          // H/y buffer [t][o], pitch 33
    float* sh2 = shw + T_DIM * HP;            // h2 buffer  [j][t], pitch 29
    const bool tl = (lane < T_DIM);

    // ---- phase 1: lane = t. acc[p] = (H[t][2p], H[t][2p+1]) ----
    ull acc[C1 / 2];
#pragma unroll
    for (int p = 0; p < C1 / 2; ++p)
        acc[p] = *reinterpret_cast<const ull*>(c_P + OFF_B1 + 2 * p);

    const float* xcol = x + (size_t)n * (F_DIM * T_DIM) + lane;
#pragma unroll 7
    for (int f = 0; f < F_DIM; ++f) {
        float xv = tl ? __ldg(xcol + f * T_DIM) : 0.0f;   // coalesced, lane-distinct
        ull xp = pack2(xv, xv);
        const ulonglong2* wq = reinterpret_cast<const ulonglong2*>(c_P + OFF_W1T + f * C1);
#pragma unroll
        for (int q = 0; q < 8; ++q) {                     // uniform const loads
            ulonglong2 w = wq[q];
            acc[2 * q]     = ffma2(xp, w.x, acc[2 * q]);
            acc[2 * q + 1] = ffma2(xp, w.y, acc[2 * q + 1]);
        }
    }
    // transpose H to shared (scalar, conflict-free: bank = t + o mod 32)
    if (tl) {
#pragma unroll
        for (int p = 0; p < C1 / 2; ++p) {
            float a, b; unpack2(acc[p], a, b);
            shw[lane * HP + 2 * p]     = a;
            shw[lane * HP + 2 * p + 1] = b;
        }
    }
    __syncwarp();

    // ---- IF scan + synapse filter: lane = o, y written in place over H ----
    {
        const float itau = c_P[OFF_ITAU];
        float v = 0.0f, g = 0.0f;
#pragma unroll
        for (int t = 0; t < T_DIM; ++t) {
            float h = shw[t * HP + lane];
            v += h;
            bool sp = (v >= 1.0f);
            v = sp ? 0.0f : v;                 // hard reset
            g = fmaf(g, -itau, g) + (sp ? 1.0f : 0.0f);
            shw[t * HP + lane] = g;            // y[t][o]
        }
    }
    __syncwarp();

    // ---- phase 2: lane = t, W2 from constant ----
    if (tl) {
        ull yq[C1 / 2];
        const float* yr = shw + lane * HP;     // row read, conflict-free scalar
#pragma unroll
        for (int q = 0; q < C1 / 2; ++q) yq[q] = pack2(yr[2 * q], yr[2 * q + 1]);
#pragma unroll
        for (int j = 0; j < C2; ++j) {
            ull a2 = 0ULL;                     // (0.f, 0.f)
            const ulonglong2* wq2 = reinterpret_cast<const ulonglong2*>(c_P + OFF_W2 + j * C1);
#pragma unroll
            for (int q = 0; q < 8; ++q) {
                ulonglong2 w = wq2[q];
                a2 = ffma2(yq[2 * q],     w.x, a2);
                a2 = ffma2(yq[2 * q + 1], w.y, a2);
            }
            float a, b; unpack2(a2, a, b);
            sh2[j * H2P + lane] = a + b + c_P[OFF_B2 + j];
        }
    }
    __syncwarp();

    // ---- second IF scan + mean: lane = j ----
    if (lane < C2) {
        float v = 0.0f, cnt = 0.0f;
#pragma unroll
        for (int t = 0; t < T_DIM; ++t) {
            v += sh2[lane * H2P + t];
            if (v >= 1.0f) { cnt += 1.0f; v = 0.0f; }
        }
        out[(size_t)n * C2 + lane] = cnt * (1.0f / 28.0f);
    }
}

extern "C" void kernel_launch(void* const* d_in, const int* in_sizes, int n_in,
                              void* d_out, int out_size)
{
    const float* x     = (const float*)d_in[0];
    const float* W1    = (const float*)d_in[1];
    const float* b1    = (const float*)d_in[2];
    const float* w_syn = (const float*)d_in[3];
    const float* W2    = (const float*)d_in[4];
    const float* b2    = (const float*)d_in[5];
    float* out = (float*)d_out;

    const int N = in_sizes[0] / (F_DIM * T_DIM);

    setup_kernel<<<1, 1024>>>(W1, b1, w_syn, W2, b2);

    void* sp = nullptr;
    cudaGetSymbolAddress(&sp, g_stage);
    cudaMemcpyToSymbolAsync(c_P, sp, CP_SIZE * sizeof(float), 0,
                            cudaMemcpyDeviceToDevice, 0);

    const int blocks = (N + WARPS - 1) / WARPS;
    snn_kernel<<<blocks, WARPS * 32>>>(x, out, N);
}